// round 10
// baseline (speedup 1.0000x reference)
#include <cuda_runtime.h>
#include <cuda_fp16.h>
#include <cstdint>

// B=16,H=128 -> 2048 groups; per group X[128,256], D=32.
#define NTHR 256

// ---------------- SMEM layout (bytes) ----------------
#define XSTR    544                  // X row stride (272 fp16 slots)
#define XP_OFF  0                    // X fp16 [128][XSTR] = 69,632
#define WB0     69632                // weight buffer 0 (17,408)
#define WCHUNK  17408
#define WB1     87040                // weight buffer 1 (17,408)
#define KH_OFF  87040                // K image [128][96] (overlays WB1)
#define KSTR    96
#define VT_OFF  104448               // V^T chunk [32][288]
#define VSTR    288
#define SMEM_BYTES 113664            // -> 2 CTAs/SM

// k-permutation: (2q,2q+1,2q+8,2q+9) contiguous per 16-block -> LDS.64 frags
__device__ __forceinline__ int kslot(int k) {
    return (k & ~15) | (((k >> 1) & 3) << 2) | (((k >> 3) & 1) << 1) | (k & 1);
}

// 10 weight-chunk images: 0=Wq, 1=Wk, 2..9=Wv col-chunks of 32
__device__ __align__(16) unsigned char g_wimg[10 * WCHUNK];

__device__ __forceinline__ uint32_t smem_u32(const void* p) {
    uint32_t a;
    asm("{ .reg .u64 t; cvta.to.shared.u64 t, %1; cvt.u32.u64 %0, t; }" : "=r"(a) : "l"(p));
    return a;
}
__device__ __forceinline__ void cp16(void* sdst, const void* gsrc) {
    asm volatile("cp.async.cg.shared.global [%0], [%1], 16;"
                 :: "r"(smem_u32(sdst)), "l"(gsrc));
}
#define CP_COMMIT() asm volatile("cp.async.commit_group;" ::: "memory")
#define CP_WAIT0()  asm volatile("cp.async.wait_group 0;" ::: "memory")

__device__ __forceinline__ void mma16816(float* c, uint32_t a0, uint32_t a1,
                                         uint32_t a2, uint32_t a3,
                                         uint32_t b0, uint32_t b1) {
    asm volatile(
        "mma.sync.aligned.m16n8k16.row.col.f32.f16.f16.f32 "
        "{%0,%1,%2,%3},{%4,%5,%6,%7},{%8,%9},{%0,%1,%2,%3};"
        : "+f"(c[0]), "+f"(c[1]), "+f"(c[2]), "+f"(c[3])
        : "r"(a0), "r"(a1), "r"(a2), "r"(a3), "r"(b0), "r"(b1));
}
__device__ __forceinline__ uint32_t packh(float x, float y) {
    __half2 p = __floats2half2_rn(x, y);
    return *reinterpret_cast<uint32_t*>(&p);
}

// =============== prep: weights -> fp16 SMEM-image chunks ===============
__global__ void prep_weights(const float* __restrict__ Wq, const float* __restrict__ Wk,
                             const float* __restrict__ Wv) {
    int idx = blockIdx.x * 256 + threadIdx.x;   // 81920 total
    int chunk = idx >> 13;
    int n = (idx >> 8) & 31;
    int k = idx & 255;
    float w;
    if (chunk == 0)      w = Wq[k * 32 + n];
    else if (chunk == 1) w = Wk[k * 32 + n];
    else                 w = Wv[k * 256 + (chunk - 2) * 32 + n];
    unsigned off = (unsigned)chunk * WCHUNK + (unsigned)n * XSTR + (unsigned)kslot(k) * 2;
    *(__half*)(g_wimg + off) = __float2half(w);
}

// =============== main: one CTA (8 warps) per (b,h) group, 2 CTAs/SM ===============
__global__ __launch_bounds__(NTHR, 2)
void attn_mma_kernel(const float* __restrict__ X,
                     const float* __restrict__ bq, const float* __restrict__ bk,
                     const float* __restrict__ bv, float* __restrict__ out) {
    extern __shared__ unsigned char sm[];
    const int t = threadIdx.x, w = t >> 5, lane = t & 31;
    const int q = lane & 3, lq = lane >> 2;
    const int R = w * 16;
    const int pr = w >> 1, h = w & 1;       // Vproj pair index / K-half
    const long long g = blockIdx.x;
    const float* Xg = X + g * 32768LL;
    float* Og = out + g * 32768LL;

    // prefetch Wq -> WB0, Wk -> WB1
    for (int i = t; i < WCHUNK / 16; i += NTHR) cp16(sm + WB0 + i * 16, g_wimg + i * 16);
    for (int i = t; i < WCHUNK / 16; i += NTHR) cp16(sm + WB1 + i * 16, g_wimg + WCHUNK + i * 16);
    CP_COMMIT();

    // X load -> fp16 permuted image
    {
        const float4* X4 = (const float4*)Xg;
        for (int i = t; i < 8192; i += NTHR) {
            int row = i >> 6, k0 = (i & 63) * 4;
            float4 f = X4[i];
            int s0 = kslot(k0), s1 = kslot(k0 + 2);
            unsigned b = (unsigned)row * XSTR;
            *(uint32_t*)(sm + XP_OFF + b + s0 * 2) = packh(f.x, f.y);
            *(uint32_t*)(sm + XP_OFF + b + s1 * 2) = packh(f.z, f.w);
        }
    }
    CP_WAIT0();
    __syncthreads();

    const unsigned char* XP0 = sm + XP_OFF + (unsigned)(R + lq) * XSTR;
    const unsigned char* XP1 = XP0 + 8 * XSTR;

    // ---------------- fused Q + K projection ----------------
    float Cq[4][4], Ck[4][4];
    #pragma unroll
    for (int n = 0; n < 4; n++) {
        Cq[n][0] = Cq[n][1] = Cq[n][2] = Cq[n][3] = 0.f;
        Ck[n][0] = Ck[n][1] = Ck[n][2] = Ck[n][3] = 0.f;
    }
    #pragma unroll 4
    for (int kt = 0; kt < 16; kt++) {
        unsigned ko = kt * 32 + q * 8;
        uint2 a0 = *(const uint2*)(XP0 + ko), a1 = *(const uint2*)(XP1 + ko);
        #pragma unroll
        for (int nt = 0; nt < 4; nt++) {
            uint2 bqf = *(const uint2*)(sm + WB0 + (unsigned)(nt * 8 + lq) * XSTR + ko);
            uint2 bkf = *(const uint2*)(sm + WB1 + (unsigned)(nt * 8 + lq) * XSTR + ko);
            mma16816(Cq[nt], a0.x, a1.x, a0.y, a1.y, bqf.x, bqf.y);
            mma16816(Ck[nt], a0.x, a1.x, a0.y, a1.y, bkf.x, bkf.y);
        }
    }
    // +bq, repack into scores A-fragments
    uint32_t qh[2][4];
    #pragma unroll
    for (int nt = 0; nt < 4; nt++) {
        float2 bb = *(const float2*)(bq + nt * 8 + 2 * q);
        Cq[nt][0] += bb.x; Cq[nt][1] += bb.y; Cq[nt][2] += bb.x; Cq[nt][3] += bb.y;
    }
    #pragma unroll
    for (int kt = 0; kt < 2; kt++) {
        qh[kt][0] = packh(Cq[2*kt][0],   Cq[2*kt][1]);
        qh[kt][1] = packh(Cq[2*kt][2],   Cq[2*kt][3]);
        qh[kt][2] = packh(Cq[2*kt+1][0], Cq[2*kt+1][1]);
        qh[kt][3] = packh(Cq[2*kt+1][2], Cq[2*kt+1][3]);
    }
    __syncthreads();   // all warps done reading WB0/WB1 as weights

    // prefetch Wv chunk 0 -> WB0 (overlaps K-image write + scores)
    for (int i = t; i < WCHUNK / 16; i += NTHR) cp16(sm + WB0 + i * 16, g_wimg + 2 * WCHUNK + i * 16);
    CP_COMMIT();

    // write K image (+bk) into WB1 region
    #pragma unroll
    for (int nt = 0; nt < 4; nt++) {
        float2 bb = *(const float2*)(bk + nt * 8 + 2 * q);
        float c0 = Ck[nt][0] + bb.x, c1 = Ck[nt][1] + bb.y;
        float c2 = Ck[nt][2] + bb.x, c3 = Ck[nt][3] + bb.y;
        int p = kslot(nt * 8 + 2 * q) * 2;
        *(uint32_t*)(sm + KH_OFF + (unsigned)(R + lq) * KSTR + p)     = packh(c0, c1);
        *(uint32_t*)(sm + KH_OFF + (unsigned)(R + lq + 8) * KSTR + p) = packh(c2, c3);
    }
    __syncthreads();

    // ---------------- scores S = Q @ K^T ----------------
    float Cs[16][4];
    #pragma unroll
    for (int n = 0; n < 16; n++) { Cs[n][0] = Cs[n][1] = Cs[n][2] = Cs[n][3] = 0.f; }
    #pragma unroll
    for (int ng = 0; ng < 4; ng++) {
        #pragma unroll
        for (int kt = 0; kt < 2; kt++) {
            unsigned ko = kt * 32 + q * 8;
            #pragma unroll
            for (int ni = 0; ni < 4; ni++) {
                int nt = ng * 4 + ni;
                uint2 bh = *(const uint2*)(sm + KH_OFF + (unsigned)(nt * 8 + lq) * KSTR + ko);
                mma16816(Cs[nt], qh[kt][0], qh[kt][1], qh[kt][2], qh[kt][3], bh.x, bh.y);
            }
        }
    }

    // ---------------- softmax (registers + quad shuffles) ----------------
    {
        float m0 = -1e30f, m1 = -1e30f;
        #pragma unroll
        for (int nt = 0; nt < 16; nt++) {
            m0 = fmaxf(m0, fmaxf(Cs[nt][0], Cs[nt][1]));
            m1 = fmaxf(m1, fmaxf(Cs[nt][2], Cs[nt][3]));
        }
        m0 = fmaxf(m0, __shfl_xor_sync(0xffffffffu, m0, 1));
        m0 = fmaxf(m0, __shfl_xor_sync(0xffffffffu, m0, 2));
        m1 = fmaxf(m1, __shfl_xor_sync(0xffffffffu, m1, 1));
        m1 = fmaxf(m1, __shfl_xor_sync(0xffffffffu, m1, 2));
        float s0 = 0.f, s1 = 0.f;
        #pragma unroll
        for (int nt = 0; nt < 16; nt++) {
            Cs[nt][0] = __expf(Cs[nt][0] - m0); Cs[nt][1] = __expf(Cs[nt][1] - m0);
            Cs[nt][2] = __expf(Cs[nt][2] - m1); Cs[nt][3] = __expf(Cs[nt][3] - m1);
            s0 += Cs[nt][0] + Cs[nt][1];
            s1 += Cs[nt][2] + Cs[nt][3];
        }
        s0 += __shfl_xor_sync(0xffffffffu, s0, 1);
        s0 += __shfl_xor_sync(0xffffffffu, s0, 2);
        s1 += __shfl_xor_sync(0xffffffffu, s1, 1);
        s1 += __shfl_xor_sync(0xffffffffu, s1, 2);
        const float i0 = 1.f / s0, i1 = 1.f / s1;
        #pragma unroll
        for (int nt = 0; nt < 16; nt++) {
            Cs[nt][0] *= i0; Cs[nt][1] *= i0; Cs[nt][2] *= i1; Cs[nt][3] *= i1;
        }
    }

    // repack attn into A-fragments
    uint32_t ah[8][4];
    #pragma unroll
    for (int kt = 0; kt < 8; kt++) {
        ah[kt][0] = packh(Cs[2*kt][0],   Cs[2*kt][1]);
        ah[kt][1] = packh(Cs[2*kt][2],   Cs[2*kt][3]);
        ah[kt][2] = packh(Cs[2*kt+1][0], Cs[2*kt+1][1]);
        ah[kt][3] = packh(Cs[2*kt+1][2], Cs[2*kt+1][3]);
    }

    // Vproj-T pair constants: pair pr covers tokens 32*pr..32*pr+31, warp h does kt-half
    const unsigned char* XPp = sm + XP_OFF + (unsigned)(32 * pr) * XSTR;

    // ---------------- 8 output-column chunks of 32 ----------------
    for (int c = 0; c < 8; c++) {
        const unsigned buf = (c & 1) ? WB1 : WB0;
        CP_WAIT0();
        __syncthreads();   // weights(c) ready; AV(c-1) done reading VT
        if (c < 7) {
            unsigned dst = (c & 1) ? WB0 : WB1;
            const unsigned char* src = g_wimg + (unsigned)(c + 3) * WCHUNK;
            for (int i = t; i < WCHUNK / 16; i += NTHR) cp16(sm + dst + i * 16, src + i * 16);
            CP_COMMIT();
        }

        // ---- Vproj-T partial: A = Wv chunk (M=32 cols), B = X (N = pair tokens),
        //      K-half h. C-frag layout lands directly in VT token-pair packing.
        float Cv[2][4][4];
        #pragma unroll
        for (int mt = 0; mt < 2; mt++)
            #pragma unroll
            for (int nt = 0; nt < 4; nt++)
                Cv[mt][nt][0] = Cv[mt][nt][1] = Cv[mt][nt][2] = Cv[mt][nt][3] = 0.f;
        #pragma unroll 4
        for (int kt2 = 0; kt2 < 8; kt2++) {
            unsigned ko = (unsigned)(8 * h + kt2) * 32 + q * 8;
            uint2 wa = *(const uint2*)(sm + buf + (unsigned)lq * XSTR + ko);
            uint2 wb = *(const uint2*)(sm + buf + (unsigned)(8 + lq) * XSTR + ko);
            uint2 wc = *(const uint2*)(sm + buf + (unsigned)(16 + lq) * XSTR + ko);
            uint2 wd = *(const uint2*)(sm + buf + (unsigned)(24 + lq) * XSTR + ko);
            #pragma unroll
            for (int nt = 0; nt < 4; nt++) {
                uint2 xb = *(const uint2*)(XPp + (unsigned)(nt * 8 + lq) * XSTR + ko);
                mma16816(Cv[0][nt], wa.x, wb.x, wa.y, wb.y, xb.x, xb.y);
                mma16816(Cv[1][nt], wc.x, wd.x, wc.y, wd.y, xb.x, xb.y);
            }
        }
        // store fp16 partials for PARTNER's token-half into VT
        #pragma unroll
        for (int i = 0; i < 2; i++) {
            int nt = 2 * (1 - h) + i;
            unsigned ts = (unsigned)kslot(32 * pr + nt * 8 + 2 * q) * 2;
            *(uint32_t*)(sm + VT_OFF + (unsigned)lq * VSTR + ts)        = packh(Cv[0][nt][0], Cv[0][nt][1]);
            *(uint32_t*)(sm + VT_OFF + (unsigned)(8 + lq) * VSTR + ts)  = packh(Cv[0][nt][2], Cv[0][nt][3]);
            *(uint32_t*)(sm + VT_OFF + (unsigned)(16 + lq) * VSTR + ts) = packh(Cv[1][nt][0], Cv[1][nt][1]);
            *(uint32_t*)(sm + VT_OFF + (unsigned)(24 + lq) * VSTR + ts) = packh(Cv[1][nt][2], Cv[1][nt][3]);
        }
        __syncthreads();
        // combine OWN token-half: load partner partial, add own, store final
        #pragma unroll
        for (int i = 0; i < 2; i++) {
            int nt = 2 * h + i;
            unsigned ts = (unsigned)kslot(32 * pr + nt * 8 + 2 * q) * 2;
            uint32_t* s0p = (uint32_t*)(sm + VT_OFF + (unsigned)lq * VSTR + ts);
            uint32_t* s1p = (uint32_t*)(sm + VT_OFF + (unsigned)(8 + lq) * VSTR + ts);
            uint32_t* s2p = (uint32_t*)(sm + VT_OFF + (unsigned)(16 + lq) * VSTR + ts);
            uint32_t* s3p = (uint32_t*)(sm + VT_OFF + (unsigned)(24 + lq) * VSTR + ts);
            float2 f0 = __half22float2(*(__half2*)s0p);
            float2 f1 = __half22float2(*(__half2*)s1p);
            float2 f2 = __half22float2(*(__half2*)s2p);
            float2 f3 = __half22float2(*(__half2*)s3p);
            *s0p = packh(Cv[0][nt][0] + f0.x, Cv[0][nt][1] + f0.y);
            *s1p = packh(Cv[0][nt][2] + f1.x, Cv[0][nt][3] + f1.y);
            *s2p = packh(Cv[1][nt][0] + f2.x, Cv[1][nt][1] + f2.y);
            *s3p = packh(Cv[1][nt][2] + f3.x, Cv[1][nt][3] + f3.y);
        }
        __syncthreads();   // VT(c) final, visible to all

        // ---- O chunk = attn @ V  (kt outer, nt inner) ----
        float Co[4][4];
        #pragma unroll
        for (int n = 0; n < 4; n++) { Co[n][0] = Co[n][1] = Co[n][2] = Co[n][3] = 0.f; }
        #pragma unroll
        for (int kt = 0; kt < 8; kt++) {
            unsigned ko = kt * 32 + q * 8;
            #pragma unroll
            for (int nt = 0; nt < 4; nt++) {
                uint2 bh = *(const uint2*)(sm + VT_OFF + (unsigned)(nt * 8 + lq) * VSTR + ko);
                mma16816(Co[nt], ah[kt][0], ah[kt][1], ah[kt][2], ah[kt][3], bh.x, bh.y);
            }
        }
        // epilogue: +bv, store (softmax rows sum to 1 -> bias adds directly)
        #pragma unroll
        for (int nt = 0; nt < 4; nt++) {
            int col = c * 32 + nt * 8 + 2 * q;
            float2 bb = *(const float2*)(bv + col);
            float2 o0 = make_float2(Co[nt][0] + bb.x, Co[nt][1] + bb.y);
            float2 o1 = make_float2(Co[nt][2] + bb.x, Co[nt][3] + bb.y);
            *(float2*)(Og + (long long)(R + lq) * 256 + col) = o0;
            *(float2*)(Og + (long long)(R + lq + 8) * 256 + col) = o1;
        }
    }
}

extern "C" void kernel_launch(void* const* d_in, const int* in_sizes, int n_in,
                              void* d_out, int out_size) {
    const float* X  = (const float*)d_in[0];
    const float* Wq = (const float*)d_in[1];
    const float* bq = (const float*)d_in[2];
    const float* Wk = (const float*)d_in[3];
    const float* bk = (const float*)d_in[4];
    const float* Wv = (const float*)d_in[5];
    const float* bv = (const float*)d_in[6];
    float* out = (float*)d_out;

    const int groups = in_sizes[0] / (128 * 256);   // 2048

    prep_weights<<<320, 256>>>(Wq, Wk, Wv);

    cudaFuncSetAttribute(attn_mma_kernel,
                         cudaFuncAttributeMaxDynamicSharedMemorySize, SMEM_BYTES);
    attn_mma_kernel<<<groups, NTHR, SMEM_BYTES>>>(X, bq, bk, bv, out);
}

// round 11
// speedup vs baseline: 1.2568x; 1.2568x over previous
#include <cuda_runtime.h>
#include <cuda_fp16.h>
#include <cstdint>

// B=16,H=128 -> 2048 groups; per group X[128,256], D=32.
#define NTHR 256

// ---------------- SMEM layout (bytes) ----------------
#define XSTR    544                  // X row stride (272 fp16 slots)
#define XP_OFF  0                    // X fp16 [128][XSTR] = 69,632
#define K_OFF   69632                // K image [128][96] = 12,288
#define KSTR    96
#define VT0_OFF 81920                // V^T chunk buf 0 [32][288] = 9,216
#define VT1_OFF 91136                // V^T chunk buf 1
#define VSTR    288
#define SMEM_BYTES 100352            // -> 2 CTAs/SM

// k-permutation: (2q,2q+1,2q+8,2q+9) contiguous per 16-block -> LDS.64 frags
__device__ __forceinline__ int kslot(int k) {
    return (k & ~15) | (((k >> 1) & 3) << 2) | (((k >> 3) & 1) << 1) | (k & 1);
}

// Frag-major weight image: [chunk 0..9][kt 0..15][nt 0..3][lane 0..31] uint2.
// chunk 0 = Wq, 1 = Wk, 2..9 = Wv column-chunks of 32.
// One warp B-frag = one coalesced 256B LDG.64.
#define FCHUNK 16384                 // 16*4*256 bytes per chunk
__device__ __align__(16) unsigned char g_wimg[10 * FCHUNK];

__device__ __forceinline__ void mma16816(float* c, uint32_t a0, uint32_t a1,
                                         uint32_t a2, uint32_t a3,
                                         uint32_t b0, uint32_t b1) {
    asm volatile(
        "mma.sync.aligned.m16n8k16.row.col.f32.f16.f16.f32 "
        "{%0,%1,%2,%3},{%4,%5,%6,%7},{%8,%9},{%0,%1,%2,%3};"
        : "+f"(c[0]), "+f"(c[1]), "+f"(c[2]), "+f"(c[3])
        : "r"(a0), "r"(a1), "r"(a2), "r"(a3), "r"(b0), "r"(b1));
}
__device__ __forceinline__ uint32_t packh(float x, float y) {
    __half2 p = __floats2half2_rn(x, y);
    return *reinterpret_cast<uint32_t*>(&p);
}

// =============== prep: weights -> fp16 frag-major image ===============
__global__ void prep_weights(const float* __restrict__ Wq, const float* __restrict__ Wk,
                             const float* __restrict__ Wv) {
    int idx = blockIdx.x * 256 + threadIdx.x;   // 10*16*4*32 = 20480 total
    if (idx >= 20480) return;
    int lane  = idx & 31;
    int nt    = (idx >> 5) & 3;
    int kt    = (idx >> 7) & 15;
    int chunk = idx >> 11;
    int lq = lane >> 2, q = lane & 3;
    int n  = nt * 8 + lq;
    int kb = kt * 16;
    int ks[4] = { kb + 2*q, kb + 2*q + 1, kb + 2*q + 8, kb + 2*q + 9 };
    __half v[4];
    #pragma unroll
    for (int i = 0; i < 4; i++) {
        float w;
        if (chunk == 0)      w = Wq[ks[i] * 32 + n];
        else if (chunk == 1) w = Wk[ks[i] * 32 + n];
        else                 w = Wv[ks[i] * 256 + (chunk - 2) * 32 + n];
        v[i] = __float2half(w);
    }
    *(uint2*)(g_wimg + ((chunk * 16 + kt) * 4 + nt) * 256 + lane * 8) =
        *reinterpret_cast<uint2*>(v);
}

// =============== main: one CTA (8 warps) per (b,h) group, 2 CTAs/SM ===============
__global__ __launch_bounds__(NTHR, 2)
void attn_mma_kernel(const float* __restrict__ X,
                     const float* __restrict__ bq, const float* __restrict__ bk,
                     const float* __restrict__ bv, float* __restrict__ out) {
    extern __shared__ unsigned char sm[];
    const int t = threadIdx.x, w = t >> 5, lane = t & 31;
    const int q = lane & 3, lq = lane >> 2;
    const int R = w * 16;
    const long long g = blockIdx.x;
    const float* Xg = X + g * 32768LL;
    float* Og = out + g * 32768LL;

    // X load -> fp16 permuted image
    {
        const float4* X4 = (const float4*)Xg;
        for (int i = t; i < 8192; i += NTHR) {
            int row = i >> 6, k0 = (i & 63) * 4;
            float4 f = X4[i];
            int s0 = kslot(k0), s1 = kslot(k0 + 2);
            unsigned b = (unsigned)row * XSTR;
            *(uint32_t*)(sm + XP_OFF + b + s0 * 2) = packh(f.x, f.y);
            *(uint32_t*)(sm + XP_OFF + b + s1 * 2) = packh(f.z, f.w);
        }
    }
    __syncthreads();

    const unsigned char* XP0 = sm + XP_OFF + (unsigned)(R + lq) * XSTR;
    const unsigned char* XP1 = XP0 + 8 * XSTR;

    // ---------------- fused Q + K projection (weights via coalesced LDG) ------
    float Cq[4][4], Ck[4][4];
    #pragma unroll
    for (int n = 0; n < 4; n++) {
        Cq[n][0] = Cq[n][1] = Cq[n][2] = Cq[n][3] = 0.f;
        Ck[n][0] = Ck[n][1] = Ck[n][2] = Ck[n][3] = 0.f;
    }
    #pragma unroll 4
    for (int kt = 0; kt < 16; kt++) {
        unsigned ko = kt * 32 + q * 8;
        uint2 a0 = *(const uint2*)(XP0 + ko), a1 = *(const uint2*)(XP1 + ko);
        #pragma unroll
        for (int nt = 0; nt < 4; nt++) {
            uint2 bqf = __ldg((const uint2*)(g_wimg + (unsigned)((kt * 4 + nt) * 256)) + lane);
            uint2 bkf = __ldg((const uint2*)(g_wimg + FCHUNK + (unsigned)((kt * 4 + nt) * 256)) + lane);
            mma16816(Cq[nt], a0.x, a1.x, a0.y, a1.y, bqf.x, bqf.y);
            mma16816(Ck[nt], a0.x, a1.x, a0.y, a1.y, bkf.x, bkf.y);
        }
    }
    // +bq, repack into scores A-fragments
    uint32_t qh[2][4];
    #pragma unroll
    for (int nt = 0; nt < 4; nt++) {
        float2 bb = *(const float2*)(bq + nt * 8 + 2 * q);
        Cq[nt][0] += bb.x; Cq[nt][1] += bb.y; Cq[nt][2] += bb.x; Cq[nt][3] += bb.y;
    }
    #pragma unroll
    for (int kt = 0; kt < 2; kt++) {
        qh[kt][0] = packh(Cq[2*kt][0],   Cq[2*kt][1]);
        qh[kt][1] = packh(Cq[2*kt][2],   Cq[2*kt][3]);
        qh[kt][2] = packh(Cq[2*kt+1][0], Cq[2*kt+1][1]);
        qh[kt][3] = packh(Cq[2*kt+1][2], Cq[2*kt+1][3]);
    }

    // write K image (+bk)
    #pragma unroll
    for (int nt = 0; nt < 4; nt++) {
        float2 bb = *(const float2*)(bk + nt * 8 + 2 * q);
        float c0 = Ck[nt][0] + bb.x, c1 = Ck[nt][1] + bb.y;
        float c2 = Ck[nt][2] + bb.x, c3 = Ck[nt][3] + bb.y;
        int p = kslot(nt * 8 + 2 * q) * 2;
        *(uint32_t*)(sm + K_OFF + (unsigned)(R + lq) * KSTR + p)     = packh(c0, c1);
        *(uint32_t*)(sm + K_OFF + (unsigned)(R + lq + 8) * KSTR + p) = packh(c2, c3);
    }
    __syncthreads();

    // ---------------- scores S = Q @ K^T ----------------
    float Cs[16][4];
    #pragma unroll
    for (int n = 0; n < 16; n++) { Cs[n][0] = Cs[n][1] = Cs[n][2] = Cs[n][3] = 0.f; }
    #pragma unroll
    for (int ng = 0; ng < 4; ng++) {
        #pragma unroll
        for (int kt = 0; kt < 2; kt++) {
            unsigned ko = kt * 32 + q * 8;
            #pragma unroll
            for (int ni = 0; ni < 4; ni++) {
                int nt = ng * 4 + ni;
                uint2 bh = *(const uint2*)(sm + K_OFF + (unsigned)(nt * 8 + lq) * KSTR + ko);
                mma16816(Cs[nt], qh[kt][0], qh[kt][1], qh[kt][2], qh[kt][3], bh.x, bh.y);
            }
        }
    }

    // ---------------- softmax (registers + quad shuffles) ----------------
    {
        float m0 = -1e30f, m1 = -1e30f;
        #pragma unroll
        for (int nt = 0; nt < 16; nt++) {
            m0 = fmaxf(m0, fmaxf(Cs[nt][0], Cs[nt][1]));
            m1 = fmaxf(m1, fmaxf(Cs[nt][2], Cs[nt][3]));
        }
        m0 = fmaxf(m0, __shfl_xor_sync(0xffffffffu, m0, 1));
        m0 = fmaxf(m0, __shfl_xor_sync(0xffffffffu, m0, 2));
        m1 = fmaxf(m1, __shfl_xor_sync(0xffffffffu, m1, 1));
        m1 = fmaxf(m1, __shfl_xor_sync(0xffffffffu, m1, 2));
        float s0 = 0.f, s1 = 0.f;
        #pragma unroll
        for (int nt = 0; nt < 16; nt++) {
            Cs[nt][0] = __expf(Cs[nt][0] - m0); Cs[nt][1] = __expf(Cs[nt][1] - m0);
            Cs[nt][2] = __expf(Cs[nt][2] - m1); Cs[nt][3] = __expf(Cs[nt][3] - m1);
            s0 += Cs[nt][0] + Cs[nt][1];
            s1 += Cs[nt][2] + Cs[nt][3];
        }
        s0 += __shfl_xor_sync(0xffffffffu, s0, 1);
        s0 += __shfl_xor_sync(0xffffffffu, s0, 2);
        s1 += __shfl_xor_sync(0xffffffffu, s1, 1);
        s1 += __shfl_xor_sync(0xffffffffu, s1, 2);
        const float i0 = 1.f / s0, i1 = 1.f / s1;
        #pragma unroll
        for (int nt = 0; nt < 16; nt++) {
            Cs[nt][0] *= i0; Cs[nt][1] *= i0; Cs[nt][2] *= i1; Cs[nt][3] *= i1;
        }
    }

    // repack attn into A-fragments
    uint32_t ah[8][4];
    #pragma unroll
    for (int kt = 0; kt < 8; kt++) {
        ah[kt][0] = packh(Cs[2*kt][0],   Cs[2*kt][1]);
        ah[kt][1] = packh(Cs[2*kt][2],   Cs[2*kt][3]);
        ah[kt][2] = packh(Cs[2*kt+1][0], Cs[2*kt+1][1]);
        ah[kt][3] = packh(Cs[2*kt+1][2], Cs[2*kt+1][3]);
    }

    // V-transpose constants
    const int j2 = 2 * (lq >> 1);
    const int pA = kslot(R + j2) * 2;        // token pair (R+j2, R+j2+1)
    const int pB = kslot(R + j2 + 8) * 2;    // token pair (R+j2+8, R+j2+9)
    const bool oddlq = (lq & 1);

    // ---------------- 8 output-column chunks of 32 (1 barrier/chunk) ----------
    #pragma unroll 1
    for (int c = 0; c < 8; c++) {
        const unsigned char* Wc = g_wimg + (unsigned)(c + 2) * FCHUNK;
        const unsigned vt = (c & 1) ? VT1_OFF : VT0_OFF;

        // V chunk = X @ Wv[:, c*32 .. c*32+31]  (B-frags via coalesced LDG)
        float Cv[4][4];
        #pragma unroll
        for (int n = 0; n < 4; n++) { Cv[n][0] = Cv[n][1] = Cv[n][2] = Cv[n][3] = 0.f; }
        #pragma unroll 4
        for (int kt = 0; kt < 16; kt++) {
            unsigned ko = kt * 32 + q * 8;
            uint2 a0 = *(const uint2*)(XP0 + ko), a1 = *(const uint2*)(XP1 + ko);
            #pragma unroll
            for (int nt = 0; nt < 4; nt++) {
                uint2 bf = __ldg((const uint2*)(Wc + (unsigned)((kt * 4 + nt) * 256)) + lane);
                mma16816(Cv[nt], a0.x, a1.x, a0.y, a1.y, bf.x, bf.y);
            }
        }
        // transpose-store V chunk: shfl.xor(4) exchange, pack fp16 pairs -> STS.32
        #pragma unroll
        for (int nt = 0; nt < 4; nt++) {
            float v0 = Cv[nt][0], v1 = Cv[nt][1], v2 = Cv[nt][2], v3 = Cv[nt][3];
            float sendA = oddlq ? v0 : v1;
            float recvA = __shfl_xor_sync(0xffffffffu, sendA, 4);
            float sendB = oddlq ? v2 : v3;
            float recvB = __shfl_xor_sync(0xffffffffu, sendB, 4);
            float a0 = oddlq ? recvA : v0, a1 = oddlq ? v1 : recvA;
            float b0 = oddlq ? recvB : v2, b1 = oddlq ? v3 : recvB;
            unsigned cc = (unsigned)(nt * 8 + 2 * q + (oddlq ? 1 : 0)) * VSTR;
            *(uint32_t*)(sm + vt + cc + pA) = packh(a0, a1);
            *(uint32_t*)(sm + vt + cc + pB) = packh(b0, b1);
        }
        __syncthreads();   // VT(c) visible; laggards finished AV(c-1)

        // O chunk = attn @ V  (kt outer, nt inner)
        float Co[4][4];
        #pragma unroll
        for (int n = 0; n < 4; n++) { Co[n][0] = Co[n][1] = Co[n][2] = Co[n][3] = 0.f; }
        #pragma unroll
        for (int kt = 0; kt < 8; kt++) {
            unsigned ko = kt * 32 + q * 8;
            #pragma unroll
            for (int nt = 0; nt < 4; nt++) {
                uint2 bh = *(const uint2*)(sm + vt + (unsigned)(nt * 8 + lq) * VSTR + ko);
                mma16816(Co[nt], ah[kt][0], ah[kt][1], ah[kt][2], ah[kt][3], bh.x, bh.y);
            }
        }
        // epilogue: +bv, store (softmax rows sum to 1 -> bias adds directly)
        #pragma unroll
        for (int nt = 0; nt < 4; nt++) {
            int col = c * 32 + nt * 8 + 2 * q;
            float2 bb = *(const float2*)(bv + col);
            float2 o0 = make_float2(Co[nt][0] + bb.x, Co[nt][1] + bb.y);
            float2 o1 = make_float2(Co[nt][2] + bb.x, Co[nt][3] + bb.y);
            *(float2*)(Og + (long long)(R + lq) * 256 + col) = o0;
            *(float2*)(Og + (long long)(R + lq + 8) * 256 + col) = o1;
        }
    }
}

extern "C" void kernel_launch(void* const* d_in, const int* in_sizes, int n_in,
                              void* d_out, int out_size) {
    const float* X  = (const float*)d_in[0];
    const float* Wq = (const float*)d_in[1];
    const float* bq = (const float*)d_in[2];
    const float* Wk = (const float*)d_in[3];
    const float* bk = (const float*)d_in[4];
    const float* Wv = (const float*)d_in[5];
    const float* bv = (const float*)d_in[6];
    float* out = (float*)d_out;

    const int groups = in_sizes[0] / (128 * 256);   // 2048

    prep_weights<<<80, 256>>>(Wq, Wk, Wv);

    cudaFuncSetAttribute(attn_mma_kernel,
                         cudaFuncAttributeMaxDynamicSharedMemorySize, SMEM_BYTES);
    attn_mma_kernel<<<groups, NTHR, SMEM_BYTES>>>(X, bq, bk, bv, out);
}